// round 1
// baseline (speedup 1.0000x reference)
#include <cuda_runtime.h>
#include <cuda_bf16.h>

// GCN_34359738415: 2-layer GraphConv (norm='both'), N=10000, E=640000,
// feats 128 -> 128(relu) -> 64, fp32.
//
// Pipeline (all linear ops reordered so the dense GEMM happens BEFORE the
// edge scatter, minimizing atomic traffic):
//   deg_out[s]++, deg_in[d]++  over edges; rs = rsqrt(max(deg,1))
//   Z1 = rs_out[r] * (X @ W1)                       (10000x128)
//   AGG1[d] += Z1[s]  over edges                    (red.global.add.v4.f32)
//   H1 = relu(rs_in[r]*AGG1 + b1)   (applied on the fly in gemm2 staging)
//   Z2 = rs_out[r] * (H1 @ W2)                      (10000x64)
//   AGG2[d] += Z2[s]  over edges
//   out = rs_in[r]*AGG2 + b2

#define MAX_N 10000
#define MAX_E 640000
#define F_IN  128
#define F_H1  128
#define F_OUT 64

// ---------------- device scratch (no allocations allowed) ----------------
__device__ float g_deg_out[MAX_N];            // then holds rsqrt(deg_out)
__device__ float g_deg_in[MAX_N];             // then holds rsqrt(deg_in)
__device__ float g_Z1[MAX_N * F_H1];
__device__ float g_AGG1[MAX_N * F_H1];
__device__ float g_Z2[MAX_N * F_OUT];
__device__ float g_AGG2[MAX_N * F_OUT];
__device__ int   g_is64;

// ---------------- index dtype detection (int32 vs int64) ------------------
// If indices are int64 (values < 10000), every odd 32-bit word (the high
// half) is zero. If int32, the odd words are random node ids in [0,10000):
// the probability all 256 samples are zero is ~0. Deterministic per input.
__global__ void detect_idx_kernel(const unsigned* __restrict__ srcw) {
    __shared__ int nz;
    if (threadIdx.x == 0) nz = 0;
    __syncthreads();
    if (srcw[2 * threadIdx.x + 1] != 0u) atomicOr(&nz, 1);
    __syncthreads();
    if (threadIdx.x == 0) g_is64 = (nz == 0) ? 1 : 0;
}

__device__ __forceinline__ int load_idx(const void* p, int e, int is64) {
    if (is64) return (int)((const long long*)p)[e];
    return ((const int*)p)[e];
}

// ---------------- zero scratch ---------------------------------------------
__global__ void init_kernel(int n) {
    int total = n * F_H1 + n * F_OUT + n + n;
    for (int i = blockIdx.x * blockDim.x + threadIdx.x; i < total;
         i += gridDim.x * blockDim.x) {
        if (i < n * F_H1)                 g_AGG1[i] = 0.f;
        else if (i < n * F_H1 + n * F_OUT) g_AGG2[i - n * F_H1] = 0.f;
        else if (i < n * F_H1 + n * F_OUT + n) g_deg_out[i - n * F_H1 - n * F_OUT] = 0.f;
        else                              g_deg_in[i - n * F_H1 - n * F_OUT - n] = 0.f;
    }
}

// ---------------- degrees ---------------------------------------------------
__global__ void degree_kernel(const void* __restrict__ src,
                              const void* __restrict__ dst, int E) {
    int is64 = g_is64;
    for (int e = blockIdx.x * blockDim.x + threadIdx.x; e < E;
         e += gridDim.x * blockDim.x) {
        atomicAdd(&g_deg_out[load_idx(src, e, is64)], 1.f);
        atomicAdd(&g_deg_in [load_idx(dst, e, is64)], 1.f);
    }
}

__global__ void rsqrt_kernel(int n) {
    int i = blockIdx.x * blockDim.x + threadIdx.x;
    if (i < n) {
        g_deg_out[i] = rsqrtf(fmaxf(g_deg_out[i], 1.f));
        g_deg_in[i]  = rsqrtf(fmaxf(g_deg_in[i], 1.f));
    }
}

// ---------------- GEMM: Z = rs_out[r] * (transform(X) @ W) ----------------
// Block of NOUT threads computes a 16-row x NOUT-col tile. X row chunk is
// staged to SMEM (with the layer-2 input transform applied during staging);
// the inner loop is broadcast-LDS + coalesced L2-resident LDG of W.
template <int NOUT, bool LAYER2>
__global__ void gemm_kernel(const float* __restrict__ X,
                            const float* __restrict__ W,
                            const float* __restrict__ rs_out,
                            const float* __restrict__ rs_in,
                            const float* __restrict__ bias,  // b1 for layer2 staging
                            float* __restrict__ Z, int n) {
    __shared__ float xs[16 * F_IN];
    const int r0 = blockIdx.x * 16;
    const int t = threadIdx.x;

    for (int i = t; i < 16 * F_IN; i += NOUT) {
        int rr = i >> 7;        // F_IN == 128
        int kk = i & 127;
        int r = r0 + rr;
        float v = 0.f;
        if (r < n) {
            v = X[r * F_IN + kk];
            if (LAYER2) v = fmaxf(fmaf(v, rs_in[r], bias[kk]), 0.f);
        }
        xs[i] = v;
    }
    __syncthreads();

    float acc[16];
#pragma unroll
    for (int r = 0; r < 16; r++) acc[r] = 0.f;

#pragma unroll 4
    for (int k = 0; k < F_IN; k++) {
        float w = __ldg(&W[k * NOUT + t]);
#pragma unroll
        for (int r = 0; r < 16; r++)
            acc[r] = fmaf(xs[r * F_IN + k], w, acc[r]);
    }

#pragma unroll
    for (int r = 0; r < 16; r++) {
        int rr = r0 + r;
        if (rr < n) Z[rr * NOUT + t] = acc[r] * rs_out[rr];
    }
}

// ---------------- edge scatter: AGG[dst] += Z[src] -------------------------
__device__ __forceinline__ void red_add_v4(float* p, float4 v) {
    asm volatile("red.global.add.v4.f32 [%0], {%1, %2, %3, %4};"
                 :: "l"(p), "f"(v.x), "f"(v.y), "f"(v.z), "f"(v.w)
                 : "memory");
}

// 128-wide: one warp per edge, one float4 RED per lane.
__global__ void scatter128_kernel(const void* __restrict__ src,
                                  const void* __restrict__ dst,
                                  const float* __restrict__ Z,
                                  float* __restrict__ AGG, int E) {
    int gid = blockIdx.x * blockDim.x + threadIdx.x;
    int e = gid >> 5;
    int lane = gid & 31;
    if (e >= E) return;
    int is64 = g_is64;
    int s = load_idx(src, e, is64);
    int d = load_idx(dst, e, is64);
    float4 v = __ldg((const float4*)(Z + (size_t)s * F_H1) + lane);
    red_add_v4(AGG + (size_t)d * F_H1 + lane * 4, v);
}

// 64-wide: half-warp per edge.
__global__ void scatter64_kernel(const void* __restrict__ src,
                                 const void* __restrict__ dst,
                                 const float* __restrict__ Z,
                                 float* __restrict__ AGG, int E) {
    int gid = blockIdx.x * blockDim.x + threadIdx.x;
    int e = gid >> 4;
    int sub = gid & 15;
    if (e >= E) return;
    int is64 = g_is64;
    int s = load_idx(src, e, is64);
    int d = load_idx(dst, e, is64);
    float4 v = __ldg((const float4*)(Z + (size_t)s * F_OUT) + sub);
    red_add_v4(AGG + (size_t)d * F_OUT + sub * 4, v);
}

// ---------------- final epilogue: out = rs_in[r]*AGG2 + b2 -----------------
__global__ void final_kernel(const float* __restrict__ b2,
                             float* __restrict__ out, int n) {
    int total = n * F_OUT;
    for (int i = blockIdx.x * blockDim.x + threadIdx.x; i < total;
         i += gridDim.x * blockDim.x) {
        int r = i / F_OUT;
        int c = i - r * F_OUT;
        out[i] = fmaf(g_AGG2[i], g_deg_in[r], b2[c]);
    }
}

// ---------------- launch ----------------------------------------------------
extern "C" void kernel_launch(void* const* d_in, const int* in_sizes, int n_in,
                              void* d_out, int out_size) {
    const float* X   = (const float*)d_in[0];
    const void*  src = d_in[1];
    const void*  dst = d_in[2];
    const float* W1  = (const float*)d_in[3];
    const float* b1  = (const float*)d_in[4];
    const float* W2  = (const float*)d_in[5];
    const float* b2  = (const float*)d_in[6];
    float* out = (float*)d_out;

    const int n = in_sizes[0] / F_IN;   // 10000
    const int E = in_sizes[1];          // 640000 (element count, any dtype)

    float *dZ1, *dAGG1, *dZ2, *dAGG2, *dRsOut, *dRsIn;
    cudaGetSymbolAddress((void**)&dZ1,    g_Z1);
    cudaGetSymbolAddress((void**)&dAGG1,  g_AGG1);
    cudaGetSymbolAddress((void**)&dZ2,    g_Z2);
    cudaGetSymbolAddress((void**)&dAGG2,  g_AGG2);
    cudaGetSymbolAddress((void**)&dRsOut, g_deg_out);
    cudaGetSymbolAddress((void**)&dRsIn,  g_deg_in);

    detect_idx_kernel<<<1, 256>>>((const unsigned*)src);

    init_kernel<<<1184, 256>>>(n);

    degree_kernel<<<(E + 255) / 256, 256>>>(src, dst, E);

    rsqrt_kernel<<<(n + 255) / 256, 256>>>(n);

    // Layer 1: Z1 = rs_out * (X @ W1)
    gemm_kernel<F_H1, false><<<(n + 15) / 16, F_H1>>>(
        X, W1, dRsOut, nullptr, nullptr, dZ1, n);

    // AGG1[dst] += Z1[src]
    {
        long long threads = (long long)E * 32;
        int blocks = (int)((threads + 255) / 256);
        scatter128_kernel<<<blocks, 256>>>(src, dst, dZ1, dAGG1, E);
    }

    // Layer 2: Z2 = rs_out * (relu(rs_in*AGG1 + b1) @ W2)
    gemm_kernel<F_OUT, true><<<(n + 15) / 16, F_OUT>>>(
        dAGG1, W2, dRsOut, dRsIn, b1, dZ2, n);

    // AGG2[dst] += Z2[src]
    {
        long long threads = (long long)E * 16;
        int blocks = (int)((threads + 255) / 256);
        scatter64_kernel<<<blocks, 256>>>(src, dst, dZ2, dAGG2, E);
    }

    final_kernel<<<(n * F_OUT + 255) / 256, 256>>>(b2, out, n);
}

// round 3
// speedup vs baseline: 1.2479x; 1.2479x over previous
#include <cuda_runtime.h>
#include <cuda_bf16.h>

// GCN_34359738415: 2-layer GraphConv (norm='both'), N=10000, E=640000,
// feats 128 -> 128(relu) -> 64, fp32.
//
// CSR design: build dst-CSR once (counting sort), then both SpMM
// aggregations are atomic-free per-destination gather-reduces with fused
// epilogues. GEMM runs BEFORE aggregation (scale/segment-sum commute with
// the right-multiply), so layer-2 aggregation is 64-wide, not 128-wide.
//
//   hist:   deg_in[d]++, deg_out[s]++                (int atomics)
//   scan:   rowptr = exscan(deg_in); rs_* = rsqrt(max(deg,1))
//   fill:   col[pos++] = src  bucketed by dst        (CSR)
//   Z1  = rs_out[r] * (X @ W1)
//   H1[d] = relu(rs_in[d] * sum_{e in CSR[d]} Z1[col[e]] + b1)
//   Z2  = rs_out[r] * (H1 @ W2)
//   out[d] = rs_in[d] * sum_{e in CSR[d]} Z2[col[e]] + b2

#define MAX_N 10000
#define MAX_E 640000
#define F_IN  128
#define F_H1  128
#define F_OUT 64

// ---------------- device scratch ----------------
__device__ int   g_deg_in[MAX_N];
__device__ int   g_deg_out[MAX_N];
__device__ int   g_rowptr[MAX_N + 1];
__device__ int   g_cursor[MAX_N];
__device__ int   g_col[MAX_E];
__device__ float g_rs_in[MAX_N];
__device__ float g_rs_out[MAX_N];
__device__ float g_Z1[MAX_N * F_H1];
__device__ float g_H1[MAX_N * F_H1];
__device__ float g_Z2[MAX_N * F_OUT];
__device__ int   g_is64;

// ---------------- idx dtype helpers ----------------
__device__ __forceinline__ int load_idx(const void* p, int e, int is64) {
    if (is64) return (int)((const long long*)p)[e];
    return ((const int*)p)[e];
}

// ---------------- zero histograms + detect int64 vs int32 ----------------
// int64 indices < 10000 => every odd 32-bit word is 0. int32 random ids =>
// essentially impossible that 256 samples of the odd words are all zero.
__global__ void zero_detect_kernel(const unsigned* __restrict__ srcw, int n) {
    int i = blockIdx.x * blockDim.x + threadIdx.x;
    if (i < n) { g_deg_in[i] = 0; g_deg_out[i] = 0; }
    if (blockIdx.x == 0) {
        __shared__ int nz;
        if (threadIdx.x == 0) nz = 0;
        __syncthreads();
        if (threadIdx.x < 256 && srcw[2 * threadIdx.x + 1] != 0u) atomicOr(&nz, 1);
        __syncthreads();
        if (threadIdx.x == 0) g_is64 = (nz == 0) ? 1 : 0;
    }
}

// ---------------- histograms ----------------
__global__ __launch_bounds__(256) void hist_kernel(const void* __restrict__ src,
                                                   const void* __restrict__ dst,
                                                   int E) {
    int is64 = g_is64;
    for (int e = blockIdx.x * blockDim.x + threadIdx.x; e < E;
         e += gridDim.x * blockDim.x) {
        atomicAdd(&g_deg_out[load_idx(src, e, is64)], 1);
        atomicAdd(&g_deg_in [load_idx(dst, e, is64)], 1);
    }
}

// ---------------- single-block scan + rsqrt scales ----------------
__global__ void scan_kernel(int n) {
    const int T = 1024, IT = 10;   // covers 10240 >= n
    int t = threadIdx.x;
    int lane = t & 31, wid = t >> 5;
    __shared__ int wsum[32];

    int base = t * IT;
    int loc[IT];
    int run = 0;
#pragma unroll
    for (int i = 0; i < IT; i++) {
        int idx = base + i;
        int v = (idx < n) ? g_deg_in[idx] : 0;
        loc[i] = run; run += v;
    }
    int inc = run;
#pragma unroll
    for (int o = 1; o < 32; o <<= 1) {
        int x = __shfl_up_sync(0xffffffffu, inc, o);
        if (lane >= o) inc += x;
    }
    if (lane == 31) wsum[wid] = inc;
    __syncthreads();
    if (wid == 0) {
        int v = wsum[lane];
#pragma unroll
        for (int o = 1; o < 32; o <<= 1) {
            int x = __shfl_up_sync(0xffffffffu, v, o);
            if (lane >= o) v += x;
        }
        wsum[lane] = v;
    }
    __syncthreads();
    int excl = inc - run + (wid > 0 ? wsum[wid - 1] : 0);
#pragma unroll
    for (int i = 0; i < IT; i++) {
        int idx = base + i;
        if (idx < n) {
            int p = excl + loc[i];
            g_rowptr[idx] = p;
            g_cursor[idx] = p;
        }
    }
    if (t == T - 1) g_rowptr[n] = excl + run;

    for (int idx = t; idx < n; idx += T) {
        g_rs_in[idx]  = rsqrtf(fmaxf((float)g_deg_in[idx],  1.f));
        g_rs_out[idx] = rsqrtf(fmaxf((float)g_deg_out[idx], 1.f));
    }
}

// ---------------- CSR fill (counting-sort bucket phase) ----------------
__global__ __launch_bounds__(256) void fill_kernel(const void* __restrict__ src,
                                                   const void* __restrict__ dst,
                                                   int E) {
    int is64 = g_is64;
    for (int e = blockIdx.x * blockDim.x + threadIdx.x; e < E;
         e += gridDim.x * blockDim.x) {
        int d = load_idx(dst, e, is64);
        int s = load_idx(src, e, is64);
        int pos = atomicAdd(&g_cursor[d], 1);
        g_col[pos] = s;
    }
}

// ---------------- GEMM: Z = rs_out[r] * (X @ W) ----------------
template <int NOUT>
__global__ void gemm_kernel(const float* __restrict__ X,
                            const float* __restrict__ W,
                            const float* __restrict__ rs_out,
                            float* __restrict__ Z, int n) {
    __shared__ float xs[16 * F_IN];
    const int r0 = blockIdx.x * 16;
    const int t = threadIdx.x;

    for (int i = t; i < 16 * F_IN; i += NOUT) {
        int rr = i >> 7;          // F_IN == 128
        int kk = i & 127;
        int r = r0 + rr;
        xs[i] = (r < n) ? X[r * F_IN + kk] : 0.f;
    }
    __syncthreads();

    float acc[16];
#pragma unroll
    for (int r = 0; r < 16; r++) acc[r] = 0.f;

#pragma unroll 4
    for (int k = 0; k < F_IN; k++) {
        float w = __ldg(&W[k * NOUT + t]);
#pragma unroll
        for (int r = 0; r < 16; r++)
            acc[r] = fmaf(xs[r * F_IN + k], w, acc[r]);
    }

#pragma unroll
    for (int r = 0; r < 16; r++) {
        int rr = r0 + r;
        if (rr < n) Z[rr * NOUT + t] = acc[r] * rs_out[rr];
    }
}

// ---------------- gather-reduce helpers ----------------
__device__ __forceinline__ void acc4(float4& a, float4 v) {
    a.x += v.x; a.y += v.y; a.z += v.z; a.w += v.w;
}
__device__ __forceinline__ void acc2(float2& a, float2 v) {
    a.x += v.x; a.y += v.y;
}

// ---------------- gather-reduce, 128 feats: one warp per dst row ----------
// H1[d] = relu(rs_in[d] * sum Z1[col[e]] + b1)
// Column indices are prefetched 32-at-a-time by the warp (one coalesced load
// per 32 edges) and distributed via shfl.
__global__ __launch_bounds__(256) void gather128_kernel(
        const float* __restrict__ Z, const float* __restrict__ b1,
        float* __restrict__ H, int n) {
    int node = blockIdx.x * (blockDim.x >> 5) + (threadIdx.x >> 5);
    if (node >= n) return;
    int lane = threadIdx.x & 31;
    int beg = g_rowptr[node], end = g_rowptr[node + 1];

    float4 a0 = {0,0,0,0}, a1 = {0,0,0,0}, a2 = {0,0,0,0}, a3 = {0,0,0,0};

    for (int base = beg; base < end; base += 32) {
        int cnt = min(32, end - base);
        int myc = (lane < cnt) ? g_col[base + lane] : 0;
        int j = 0;
        for (; j + 4 <= cnt; j += 4) {
            int s0 = __shfl_sync(0xffffffffu, myc, j);
            int s1 = __shfl_sync(0xffffffffu, myc, j + 1);
            int s2 = __shfl_sync(0xffffffffu, myc, j + 2);
            int s3 = __shfl_sync(0xffffffffu, myc, j + 3);
            float4 v0 = __ldg((const float4*)(Z + (size_t)s0 * F_H1) + lane);
            float4 v1 = __ldg((const float4*)(Z + (size_t)s1 * F_H1) + lane);
            float4 v2 = __ldg((const float4*)(Z + (size_t)s2 * F_H1) + lane);
            float4 v3 = __ldg((const float4*)(Z + (size_t)s3 * F_H1) + lane);
            acc4(a0, v0); acc4(a1, v1); acc4(a2, v2); acc4(a3, v3);
        }
        for (; j < cnt; j++) {
            int s = __shfl_sync(0xffffffffu, myc, j);
            acc4(a0, __ldg((const float4*)(Z + (size_t)s * F_H1) + lane));
        }
    }
    acc4(a0, a1); acc4(a2, a3); acc4(a0, a2);

    float ri = g_rs_in[node];
    float4 bb = __ldg((const float4*)b1 + lane);
    float4 o;
    o.x = fmaxf(fmaf(a0.x, ri, bb.x), 0.f);
    o.y = fmaxf(fmaf(a0.y, ri, bb.y), 0.f);
    o.z = fmaxf(fmaf(a0.z, ri, bb.z), 0.f);
    o.w = fmaxf(fmaf(a0.w, ri, bb.w), 0.f);
    ((float4*)(H + (size_t)node * F_H1))[lane] = o;
}

// ---------------- gather-reduce, 64 feats: one warp per dst row ----------
// out[d] = rs_in[d] * sum Z2[col[e]] + b2
__global__ __launch_bounds__(256) void gather64_kernel(
        const float* __restrict__ Z, const float* __restrict__ b2,
        float* __restrict__ out, int n) {
    int node = blockIdx.x * (blockDim.x >> 5) + (threadIdx.x >> 5);
    if (node >= n) return;
    int lane = threadIdx.x & 31;
    int beg = g_rowptr[node], end = g_rowptr[node + 1];

    float2 a0 = {0,0}, a1 = {0,0}, a2 = {0,0}, a3 = {0,0};

    for (int base = beg; base < end; base += 32) {
        int cnt = min(32, end - base);
        int myc = (lane < cnt) ? g_col[base + lane] : 0;
        int j = 0;
        for (; j + 4 <= cnt; j += 4) {
            int s0 = __shfl_sync(0xffffffffu, myc, j);
            int s1 = __shfl_sync(0xffffffffu, myc, j + 1);
            int s2 = __shfl_sync(0xffffffffu, myc, j + 2);
            int s3 = __shfl_sync(0xffffffffu, myc, j + 3);
            float2 v0 = __ldg((const float2*)(Z + (size_t)s0 * F_OUT) + lane);
            float2 v1 = __ldg((const float2*)(Z + (size_t)s1 * F_OUT) + lane);
            float2 v2 = __ldg((const float2*)(Z + (size_t)s2 * F_OUT) + lane);
            float2 v3 = __ldg((const float2*)(Z + (size_t)s3 * F_OUT) + lane);
            acc2(a0, v0); acc2(a1, v1); acc2(a2, v2); acc2(a3, v3);
        }
        for (; j < cnt; j++) {
            int s = __shfl_sync(0xffffffffu, myc, j);
            acc2(a0, __ldg((const float2*)(Z + (size_t)s * F_OUT) + lane));
        }
    }
    acc2(a0, a1); acc2(a2, a3); acc2(a0, a2);

    float ri = g_rs_in[node];
    float2 bb = __ldg((const float2*)b2 + lane);
    float2 o;
    o.x = fmaf(a0.x, ri, bb.x);
    o.y = fmaf(a0.y, ri, bb.y);
    ((float2*)(out + (size_t)node * F_OUT))[lane] = o;
}

// ---------------- launch ----------------
extern "C" void kernel_launch(void* const* d_in, const int* in_sizes, int n_in,
                              void* d_out, int out_size) {
    const float* X   = (const float*)d_in[0];
    const void*  src = d_in[1];
    const void*  dst = d_in[2];
    const float* W1  = (const float*)d_in[3];
    const float* b1  = (const float*)d_in[4];
    const float* W2  = (const float*)d_in[5];
    const float* b2  = (const float*)d_in[6];
    float* out = (float*)d_out;

    const int n = in_sizes[0] / F_IN;   // 10000
    const int E = in_sizes[1];          // 640000

    float *dZ1, *dH1, *dZ2, *dRsOut;
    cudaGetSymbolAddress((void**)&dZ1,    g_Z1);
    cudaGetSymbolAddress((void**)&dH1,    g_H1);
    cudaGetSymbolAddress((void**)&dZ2,    g_Z2);
    cudaGetSymbolAddress((void**)&dRsOut, g_rs_out);

    zero_detect_kernel<<<(n + 255) / 256, 256>>>((const unsigned*)src, n);

    hist_kernel<<<(E + 511) / 512, 256>>>(src, dst, E);

    scan_kernel<<<1, 1024>>>(n);

    fill_kernel<<<(E + 511) / 512, 256>>>(src, dst, E);

    // Layer 1 GEMM: Z1 = rs_out * (X @ W1)
    gemm_kernel<F_H1><<<(n + 15) / 16, F_H1>>>(X, W1, dRsOut, dZ1, n);

    // Layer 1 aggregation + epilogue: H1 = relu(rs_in * gather(Z1) + b1)
    gather128_kernel<<<(n * 32 + 255) / 256, 256>>>(dZ1, b1, dH1, n);

    // Layer 2 GEMM: Z2 = rs_out * (H1 @ W2)
    gemm_kernel<F_OUT><<<(n + 15) / 16, F_OUT>>>(dH1, W2, dRsOut, dZ2, n);

    // Layer 2 aggregation + epilogue: out = rs_in * gather(Z2) + b2
    gather64_kernel<<<(n * 32 + 255) / 256, 256>>>(dZ2, b2, out, n);
}

// round 6
// speedup vs baseline: 1.2505x; 1.0021x over previous
#include <cuda_runtime.h>
#include <cuda_bf16.h>

// GCN_34359738415: 2-layer GraphConv (norm='both'), N=10000, E=640000,
// feats 128 -> 128(relu) -> 64, fp32.
//
// CSR design: build dst-CSR once (counting sort, MLP-4 vectorized), then both
// SpMM aggregations are atomic-free per-destination gather-reduces with fused
// epilogues. GEMM runs BEFORE aggregation (scale/segment-sum commute with the
// right-multiply), so layer-2 aggregation is 64-wide, not 128-wide.

#define MAX_N 10000
#define MAX_E 640000
#define F_IN  128
#define F_H1  128
#define F_OUT 64

// ---------------- device scratch ----------------
__device__ int   g_deg_in[MAX_N];
__device__ int   g_deg_out[MAX_N];
__device__ int   g_rowptr[MAX_N + 1];
__device__ int   g_cursor[MAX_N];
__device__ int   g_col[MAX_E];
__device__ float g_rs_in[MAX_N];
__device__ float g_rs_out[MAX_N];
__device__ float g_Z1[MAX_N * F_H1];
__device__ float g_H1[MAX_N * F_H1];
__device__ float g_Z2[MAX_N * F_OUT];
__device__ int   g_is64;

// ---------------- idx dtype helpers ----------------
__device__ __forceinline__ int load_idx(const void* p, int e, int is64) {
    if (is64) return (int)((const long long*)p)[e];
    return ((const int*)p)[e];
}

// Load 4 consecutive indices starting at edge 4*i (vectorized).
__device__ __forceinline__ void load_idx4(const void* p, int i, int is64,
                                          int& v0, int& v1, int& v2, int& v3) {
    if (is64) {
        longlong2 a = ((const longlong2*)p)[2 * i];
        longlong2 b = ((const longlong2*)p)[2 * i + 1];
        v0 = (int)a.x; v1 = (int)a.y; v2 = (int)b.x; v3 = (int)b.y;
    } else {
        int4 a = ((const int4*)p)[i];
        v0 = a.x; v1 = a.y; v2 = a.z; v3 = a.w;
    }
}

// ---------------- zero histograms + detect int64 vs int32 ----------------
// int64 indices < 10000 => every odd 32-bit word is 0. int32 random ids =>
// essentially impossible that 256 samples of the odd words are all zero.
__global__ void zero_detect_kernel(const unsigned* __restrict__ srcw, int n) {
    int i = blockIdx.x * blockDim.x + threadIdx.x;
    if (i < n) { g_deg_in[i] = 0; g_deg_out[i] = 0; }
    if (blockIdx.x == 0) {
        __shared__ int nz;
        if (threadIdx.x == 0) nz = 0;
        __syncthreads();
        if (threadIdx.x < 256 && srcw[2 * threadIdx.x + 1] != 0u) atomicOr(&nz, 1);
        __syncthreads();
        if (threadIdx.x == 0) g_is64 = (nz == 0) ? 1 : 0;
    }
}

// ---------------- histograms: 4 edges/thread, independent atomics ----------
__global__ __launch_bounds__(256) void hist_kernel(const void* __restrict__ src,
                                                   const void* __restrict__ dst,
                                                   int E) {
    int i = blockIdx.x * blockDim.x + threadIdx.x;
    int is64 = g_is64;
    int e = i * 4;
    if (e + 4 <= E) {
        int s0, s1, s2, s3, d0, d1, d2, d3;
        load_idx4(src, i, is64, s0, s1, s2, s3);
        load_idx4(dst, i, is64, d0, d1, d2, d3);
        atomicAdd(&g_deg_out[s0], 1); atomicAdd(&g_deg_out[s1], 1);
        atomicAdd(&g_deg_out[s2], 1); atomicAdd(&g_deg_out[s3], 1);
        atomicAdd(&g_deg_in[d0], 1);  atomicAdd(&g_deg_in[d1], 1);
        atomicAdd(&g_deg_in[d2], 1);  atomicAdd(&g_deg_in[d3], 1);
    } else {
        for (; e < E; e++) {
            atomicAdd(&g_deg_out[load_idx(src, e, is64)], 1);
            atomicAdd(&g_deg_in [load_idx(dst, e, is64)], 1);
        }
    }
}

// ---------------- single-block scan + rsqrt scales ----------------
__global__ void scan_kernel(int n) {
    const int T = 1024, IT = 10;   // covers 10240 >= n
    int t = threadIdx.x;
    int lane = t & 31, wid = t >> 5;
    __shared__ int wsum[32];

    int base = t * IT;
    int loc[IT];
    int run = 0;
#pragma unroll
    for (int i = 0; i < IT; i++) {
        int idx = base + i;
        int v = (idx < n) ? g_deg_in[idx] : 0;
        loc[i] = run; run += v;
    }
    int inc = run;
#pragma unroll
    for (int o = 1; o < 32; o <<= 1) {
        int x = __shfl_up_sync(0xffffffffu, inc, o);
        if (lane >= o) inc += x;
    }
    if (lane == 31) wsum[wid] = inc;
    __syncthreads();
    if (wid == 0) {
        int v = wsum[lane];
#pragma unroll
        for (int o = 1; o < 32; o <<= 1) {
            int x = __shfl_up_sync(0xffffffffu, v, o);
            if (lane >= o) v += x;
        }
        wsum[lane] = v;
    }
    __syncthreads();
    int excl = inc - run + (wid > 0 ? wsum[wid - 1] : 0);
#pragma unroll
    for (int i = 0; i < IT; i++) {
        int idx = base + i;
        if (idx < n) {
            int p = excl + loc[i];
            g_rowptr[idx] = p;
            g_cursor[idx] = p;
        }
    }
    if (t == T - 1) g_rowptr[n] = excl + run;

    for (int idx = t; idx < n; idx += T) {
        g_rs_in[idx]  = rsqrtf(fmaxf((float)g_deg_in[idx],  1.f));
        g_rs_out[idx] = rsqrtf(fmaxf((float)g_deg_out[idx], 1.f));
    }
}

// ---------------- CSR fill: 4 edges/thread, overlapped atomic returns ------
__global__ __launch_bounds__(256) void fill_kernel(const void* __restrict__ src,
                                                   const void* __restrict__ dst,
                                                   int E) {
    int i = blockIdx.x * blockDim.x + threadIdx.x;
    int is64 = g_is64;
    int e = i * 4;
    if (e + 4 <= E) {
        int s0, s1, s2, s3, d0, d1, d2, d3;
        load_idx4(src, i, is64, s0, s1, s2, s3);
        load_idx4(dst, i, is64, d0, d1, d2, d3);
        int p0 = atomicAdd(&g_cursor[d0], 1);
        int p1 = atomicAdd(&g_cursor[d1], 1);
        int p2 = atomicAdd(&g_cursor[d2], 1);
        int p3 = atomicAdd(&g_cursor[d3], 1);
        g_col[p0] = s0; g_col[p1] = s1; g_col[p2] = s2; g_col[p3] = s3;
    } else {
        for (; e < E; e++) {
            int d = load_idx(dst, e, is64);
            int s = load_idx(src, e, is64);
            int pos = atomicAdd(&g_cursor[d], 1);
            g_col[pos] = s;
        }
    }
}

// ---------------- GEMM: Z = rs_out[r] * (X @ W) ----------------
template <int NOUT>
__global__ void gemm_kernel(const float* __restrict__ X,
                            const float* __restrict__ W,
                            const float* __restrict__ rs_out,
                            float* __restrict__ Z, int n) {
    __shared__ float xs[16 * F_IN];
    const int r0 = blockIdx.x * 16;
    const int t = threadIdx.x;

    for (int i = t; i < 16 * F_IN; i += NOUT) {
        int rr = i >> 7;          // F_IN == 128
        int kk = i & 127;
        int r = r0 + rr;
        xs[i] = (r < n) ? X[r * F_IN + kk] : 0.f;
    }
    __syncthreads();

    float acc[16];
#pragma unroll
    for (int r = 0; r < 16; r++) acc[r] = 0.f;

#pragma unroll 4
    for (int k = 0; k < F_IN; k++) {
        float w = __ldg(&W[k * NOUT + t]);
#pragma unroll
        for (int r = 0; r < 16; r++)
            acc[r] = fmaf(xs[r * F_IN + k], w, acc[r]);
    }

#pragma unroll
    for (int r = 0; r < 16; r++) {
        int rr = r0 + r;
        if (rr < n) Z[rr * NOUT + t] = acc[r] * rs_out[rr];
    }
}

// ---------------- gather-reduce helpers ----------------
__device__ __forceinline__ void acc4(float4& a, float4 v) {
    a.x += v.x; a.y += v.y; a.z += v.z; a.w += v.w;
}
__device__ __forceinline__ void acc2(float2& a, float2 v) {
    a.x += v.x; a.y += v.y;
}

// ---------------- gather-reduce, 128 feats: one warp per dst row ----------
// H1[d] = relu(rs_in[d] * sum Z1[col[e]] + b1)
// Column indices prefetched 32-at-a-time (one coalesced load per 32 edges)
// and distributed via shfl; inner unroll 8 for MLP.
__global__ __launch_bounds__(256) void gather128_kernel(
        const float* __restrict__ Z, const float* __restrict__ b1,
        float* __restrict__ H, int n) {
    int node = blockIdx.x * (blockDim.x >> 5) + (threadIdx.x >> 5);
    if (node >= n) return;
    int lane = threadIdx.x & 31;
    int beg = g_rowptr[node], end = g_rowptr[node + 1];

    float4 a0 = {0,0,0,0}, a1 = {0,0,0,0}, a2 = {0,0,0,0}, a3 = {0,0,0,0};
    float4 a4 = {0,0,0,0}, a5 = {0,0,0,0}, a6 = {0,0,0,0}, a7 = {0,0,0,0};

    for (int base = beg; base < end; base += 32) {
        int cnt = min(32, end - base);
        int myc = (lane < cnt) ? g_col[base + lane] : 0;
        int j = 0;
        for (; j + 8 <= cnt; j += 8) {
            int s0 = __shfl_sync(0xffffffffu, myc, j);
            int s1 = __shfl_sync(0xffffffffu, myc, j + 1);
            int s2 = __shfl_sync(0xffffffffu, myc, j + 2);
            int s3 = __shfl_sync(0xffffffffu, myc, j + 3);
            int s4 = __shfl_sync(0xffffffffu, myc, j + 4);
            int s5 = __shfl_sync(0xffffffffu, myc, j + 5);
            int s6 = __shfl_sync(0xffffffffu, myc, j + 6);
            int s7 = __shfl_sync(0xffffffffu, myc, j + 7);
            float4 v0 = __ldg((const float4*)(Z + (size_t)s0 * F_H1) + lane);
            float4 v1 = __ldg((const float4*)(Z + (size_t)s1 * F_H1) + lane);
            float4 v2 = __ldg((const float4*)(Z + (size_t)s2 * F_H1) + lane);
            float4 v3 = __ldg((const float4*)(Z + (size_t)s3 * F_H1) + lane);
            float4 v4 = __ldg((const float4*)(Z + (size_t)s4 * F_H1) + lane);
            float4 v5 = __ldg((const float4*)(Z + (size_t)s5 * F_H1) + lane);
            float4 v6 = __ldg((const float4*)(Z + (size_t)s6 * F_H1) + lane);
            float4 v7 = __ldg((const float4*)(Z + (size_t)s7 * F_H1) + lane);
            acc4(a0, v0); acc4(a1, v1); acc4(a2, v2); acc4(a3, v3);
            acc4(a4, v4); acc4(a5, v5); acc4(a6, v6); acc4(a7, v7);
        }
        for (; j < cnt; j++) {
            int s = __shfl_sync(0xffffffffu, myc, j);
            acc4(a0, __ldg((const float4*)(Z + (size_t)s * F_H1) + lane));
        }
    }
    acc4(a0, a1); acc4(a2, a3); acc4(a4, a5); acc4(a6, a7);
    acc4(a0, a2); acc4(a4, a6); acc4(a0, a4);

    float ri = g_rs_in[node];
    float4 bb = __ldg((const float4*)b1 + lane);
    float4 o;
    o.x = fmaxf(fmaf(a0.x, ri, bb.x), 0.f);
    o.y = fmaxf(fmaf(a0.y, ri, bb.y), 0.f);
    o.z = fmaxf(fmaf(a0.z, ri, bb.z), 0.f);
    o.w = fmaxf(fmaf(a0.w, ri, bb.w), 0.f);
    ((float4*)(H + (size_t)node * F_H1))[lane] = o;
}

// ---------------- gather-reduce, 64 feats: one warp per dst row ----------
// out[d] = rs_in[d] * sum Z2[col[e]] + b2
__global__ __launch_bounds__(256) void gather64_kernel(
        const float* __restrict__ Z, const float* __restrict__ b2,
        float* __restrict__ out, int n) {
    int node = blockIdx.x * (blockDim.x >> 5) + (threadIdx.x >> 5);
    if (node >= n) return;
    int lane = threadIdx.x & 31;
    int beg = g_rowptr[node], end = g_rowptr[node + 1];

    float2 a0 = {0,0}, a1 = {0,0}, a2 = {0,0}, a3 = {0,0};
    float2 a4 = {0,0}, a5 = {0,0}, a6 = {0,0}, a7 = {0,0};

    for (int base = beg; base < end; base += 32) {
        int cnt = min(32, end - base);
        int myc = (lane < cnt) ? g_col[base + lane] : 0;
        int j = 0;
        for (; j + 8 <= cnt; j += 8) {
            int s0 = __shfl_sync(0xffffffffu, myc, j);
            int s1 = __shfl_sync(0xffffffffu, myc, j + 1);
            int s2 = __shfl_sync(0xffffffffu, myc, j + 2);
            int s3 = __shfl_sync(0xffffffffu, myc, j + 3);
            int s4 = __shfl_sync(0xffffffffu, myc, j + 4);
            int s5 = __shfl_sync(0xffffffffu, myc, j + 5);
            int s6 = __shfl_sync(0xffffffffu, myc, j + 6);
            int s7 = __shfl_sync(0xffffffffu, myc, j + 7);
            float2 v0 = __ldg((const float2*)(Z + (size_t)s0 * F_OUT) + lane);
            float2 v1 = __ldg((const float2*)(Z + (size_t)s1 * F_OUT) + lane);
            float2 v2 = __ldg((const float2*)(Z + (size_t)s2 * F_OUT) + lane);
            float2 v3 = __ldg((const float2*)(Z + (size_t)s3 * F_OUT) + lane);
            float2 v4 = __ldg((const float2*)(Z + (size_t)s4 * F_OUT) + lane);
            float2 v5 = __ldg((const float2*)(Z + (size_t)s5 * F_OUT) + lane);
            float2 v6 = __ldg((const float2*)(Z + (size_t)s6 * F_OUT) + lane);
            float2 v7 = __ldg((const float2*)(Z + (size_t)s7 * F_OUT) + lane);
            acc2(a0, v0); acc2(a1, v1); acc2(a2, v2); acc2(a3, v3);
            acc2(a4, v4); acc2(a5, v5); acc2(a6, v6); acc2(a7, v7);
        }
        for (; j < cnt; j++) {
            int s = __shfl_sync(0xffffffffu, myc, j);
            acc2(a0, __ldg((const float2*)(Z + (size_t)s * F_OUT) + lane));
        }
    }
    acc2(a0, a1); acc2(a2, a3); acc2(a4, a5); acc2(a6, a7);
    acc2(a0, a2); acc2(a4, a6); acc2(a0, a4);

    float ri = g_rs_in[node];
    float2 bb = __ldg((const float2*)b2 + lane);
    float2 o;
    o.x = fmaf(a0.x, ri, bb.x);
    o.y = fmaf(a0.y, ri, bb.y);
    ((float2*)(out + (size_t)node * F_OUT))[lane] = o;
}

// ---------------- launch ----------------
extern "C" void kernel_launch(void* const* d_in, const int* in_sizes, int n_in,
                              void* d_out, int out_size) {
    const float* X   = (const float*)d_in[0];
    const void*  src = d_in[1];
    const void*  dst = d_in[2];
    const float* W1  = (const float*)d_in[3];
    const float* b1  = (const float*)d_in[4];
    const float* W2  = (const float*)d_in[5];
    const float* b2  = (const float*)d_in[6];
    float* out = (float*)d_out;

    const int n = in_sizes[0] / F_IN;   // 10000
    const int E = in_sizes[1];          // 640000

    float *dZ1, *dH1, *dZ2, *dRsOut;
    cudaGetSymbolAddress((void**)&dZ1,    g_Z1);
    cudaGetSymbolAddress((void**)&dH1,    g_H1);
    cudaGetSymbolAddress((void**)&dZ2,    g_Z2);
    cudaGetSymbolAddress((void**)&dRsOut, g_rs_out);

    zero_detect_kernel<<<(n + 255) / 256, 256>>>((const unsigned*)src, n);

    int ethreads = (E + 3) / 4;
    hist_kernel<<<(ethreads + 255) / 256, 256>>>(src, dst, E);

    scan_kernel<<<1, 1024>>>(n);

    fill_kernel<<<(ethreads + 255) / 256, 256>>>(src, dst, E);

    // Layer 1 GEMM: Z1 = rs_out * (X @ W1)
    gemm_kernel<F_H1><<<(n + 15) / 16, F_H1>>>(X, W1, dRsOut, dZ1, n);

    // Layer 1 aggregation + epilogue: H1 = relu(rs_in * gather(Z1) + b1)
    gather128_kernel<<<(n * 32 + 255) / 256, 256>>>(dZ1, b1, dH1, n);

    // Layer 2 GEMM: Z2 = rs_out * (H1 @ W2)
    gemm_kernel<F_OUT><<<(n + 15) / 16, F_OUT>>>(dH1, W2, dRsOut, dZ2, n);

    // Layer 2 aggregation + epilogue: out = rs_in * gather(Z2) + b2
    gather64_kernel<<<(n * 32 + 255) / 256, 256>>>(dZ2, b2, out, n);
}